// round 1
// baseline (speedup 1.0000x reference)
#include <cuda_runtime.h>
#include <math.h>
#include <stdint.h>

// Problem dims (fixed by the dataset)
#define BATCH 2048
#define INF   1024
#define OUTF  2048
#define LAMBDA 0.2f
#define ADMM_ITERS 100
#define NEWTON_ITERS 12

// ---------------- scratch (no allocations allowed) ----------------
__device__ float g_M  [OUTF * OUTF];
__device__ float g_Xa [OUTF * OUTF];
__device__ float g_Xb [OUTF * OUTF];
__device__ float g_T  [OUTF * OUTF];
__device__ float g_Atb[BATCH * OUTF];
__device__ float g_z0 [BATCH * OUTF];
__device__ float g_u0 [BATCH * OUTF];
__device__ float g_z1 [BATCH * OUTF];
__device__ float g_u1 [BATCH * OUTF];
__device__ unsigned int g_snorm;

// ---------------- tiny helper kernels ----------------
__global__ void reset_scalar_kernel() { g_snorm = 0u; }

// max over rows of sum_j |M[row][j]|  ->  certified upper bound on lambda_max(M)
__global__ void row_abs_sum_max_kernel(const float* __restrict__ Mm, int n) {
    __shared__ float sh[256];
    int row = blockIdx.x;
    float s = 0.f;
    for (int c = threadIdx.x; c < n; c += 256) s += fabsf(Mm[row * n + c]);
    sh[threadIdx.x] = s;
    __syncthreads();
    for (int off = 128; off > 0; off >>= 1) {
        if (threadIdx.x < off) sh[threadIdx.x] += sh[threadIdx.x + off];
        __syncthreads();
    }
    if (threadIdx.x == 0) atomicMax(&g_snorm, __float_as_uint(sh[0]));
}

// X0 = (2 / (s + 1)) * I   (lambda_min(M) >= 1, s >= lambda_max(M))
__global__ void init_X_kernel(float* __restrict__ X, int n) {
    int idx = blockIdx.x * blockDim.x + threadIdx.x;
    int r = idx / n, c = idx - r * n;
    float s = __uint_as_float(g_snorm);
    float cc = 2.0f / (s + 1.0f);
    X[idx] = (r == c) ? cc : 0.0f;
}

__global__ void zero2_kernel(float* __restrict__ a, float* __restrict__ b) {
    int idx = blockIdx.x * blockDim.x + threadIdx.x;
    float4 z = make_float4(0.f, 0.f, 0.f, 0.f);
    ((float4*)a)[idx] = z;
    ((float4*)b)[idx] = z;
}

// ---------------- the workhorse SGEMM ----------------
// C(Md x Nd) = alpha * Afused(Md x Kd) @ opB(Kd x Nd) [+ beta*D + diag*I]   (MODE_EPI==0)
//   Afused = A0                      (MODE_A==0)
//   Afused = A0 + A1 - A2            (MODE_A==1)   (ADMM prologue: Atb + z - u)
// MODE_EPI==1 : ADMM epilogue. x = acc; zu = x + Uin; z = soft(zu, LAMBDA);
//               Cout = z; Uout = zu - z.
// TRANSB: B given row-major (Nd x Kd); logical opB = B^T.
// Requires Md,Nd % 128 == 0, Kd % 16 == 0.
template <bool TRANSB, int MODE_A, int MODE_EPI>
__global__ __launch_bounds__(256, 2)
void sgemm_kernel(const float* __restrict__ A0, const float* __restrict__ A1,
                  const float* __restrict__ A2, const float* __restrict__ B,
                  const float* __restrict__ D,  const float* __restrict__ Uin,
                  float* __restrict__ Cout, float* __restrict__ Uout,
                  int Md, int Nd, int Kd, float alpha, float beta, float diag) {
    constexpr int BM = 128, BN = 128, BK = 16;
    __shared__ float As[BK][BM];
    __shared__ float Bs[BK][BN];

    const int tid = threadIdx.x;
    const int row0 = blockIdx.y * BM;
    const int col0 = blockIdx.x * BN;
    const int tx = tid & 15;   // 0..15 -> 8 cols each
    const int ty = tid >> 4;   // 0..15 -> 8 rows each

    // A-tile load mapping: 128 rows x 16 k, 8 elems/thread (2x float4)
    const int aRow = tid >> 1;          // 0..127
    const int aSeg = (tid & 1) * 8;     // 0 or 8
    // B-tile (TRANSB) mapping
    const int bRow = tid >> 1;          // 0..127 (n index)
    const int bSeg = (tid & 1) * 8;     // 0 or 8 (k index)

    float acc[8][8];
#pragma unroll
    for (int i = 0; i < 8; i++)
#pragma unroll
        for (int j = 0; j < 8; j++) acc[i][j] = 0.f;

    for (int k0 = 0; k0 < Kd; k0 += BK) {
        // ---- load A tile (transposed into As[k][m]) ----
#pragma unroll
        for (int h = 0; h < 2; h++) {
            int kc = aSeg + h * 4;
            int gidx = (row0 + aRow) * Kd + k0 + kc;
            float4 va = *(const float4*)(A0 + gidx);
            if (MODE_A == 1) {
                float4 v1 = *(const float4*)(A1 + gidx);
                float4 v2 = *(const float4*)(A2 + gidx);
                va.x += v1.x - v2.x;
                va.y += v1.y - v2.y;
                va.z += v1.z - v2.z;
                va.w += v1.w - v2.w;
            }
            As[kc + 0][aRow] = va.x;
            As[kc + 1][aRow] = va.y;
            As[kc + 2][aRow] = va.z;
            As[kc + 3][aRow] = va.w;
        }
        // ---- load B tile into Bs[k][n] ----
        if (!TRANSB) {
#pragma unroll
            for (int h = 0; h < 2; h++) {
                int v = tid * 2 + h;
                int br = v >> 5;            // 0..15 (k)
                int bc = (v & 31) * 4;      // 0..124 (n)
                float4 vb = *(const float4*)(B + (k0 + br) * Nd + col0 + bc);
                *(float4*)(&Bs[br][bc]) = vb;
            }
        } else {
#pragma unroll
            for (int h = 0; h < 2; h++) {
                int kk = bSeg + h * 4;
                float4 vb = *(const float4*)(B + (col0 + bRow) * Kd + k0 + kk);
                Bs[kk + 0][bRow] = vb.x;
                Bs[kk + 1][bRow] = vb.y;
                Bs[kk + 2][bRow] = vb.z;
                Bs[kk + 3][bRow] = vb.w;
            }
        }
        __syncthreads();

        // ---- compute ----
#pragma unroll
        for (int kk = 0; kk < BK; kk++) {
            float ra[8], rb[8];
            *(float4*)(ra)     = *(const float4*)(&As[kk][ty * 8]);
            *(float4*)(ra + 4) = *(const float4*)(&As[kk][ty * 8 + 4]);
            *(float4*)(rb)     = *(const float4*)(&Bs[kk][tx * 8]);
            *(float4*)(rb + 4) = *(const float4*)(&Bs[kk][tx * 8 + 4]);
#pragma unroll
            for (int i = 0; i < 8; i++)
#pragma unroll
                for (int j = 0; j < 8; j++) acc[i][j] = fmaf(ra[i], rb[j], acc[i][j]);
        }
        __syncthreads();
    }

    // ---- epilogue ----
#pragma unroll
    for (int i = 0; i < 8; i++) {
        int r = row0 + ty * 8 + i;
#pragma unroll
        for (int j = 0; j < 8; j++) {
            int c = col0 + tx * 8 + j;
            int idx = r * Nd + c;
            if (MODE_EPI == 0) {
                float v = alpha * acc[i][j];
                if (D != nullptr) v = fmaf(beta, D[idx], v);
                if (r == c) v += diag;
                Cout[idx] = v;
            } else {
                float zu = acc[i][j] + Uin[idx];
                float az = fabsf(zu) - LAMBDA;
                float z  = (az > 0.f) ? copysignf(az, zu) : 0.f;
                Cout[idx] = z;        // new z
                Uout[idx] = zu - z;   // new u
            }
        }
    }
}

// ---------------- host orchestration ----------------
extern "C" void kernel_launch(void* const* d_in, const int* in_sizes, int n_in,
                              void* d_out, int out_size) {
    (void)in_sizes; (void)n_in; (void)out_size;
    const float* x = (const float*)d_in[0];   // (2048, 1024)
    const float* W = (const float*)d_in[1];   // (2048, 1024) row-normalized
    float* out = (float*)d_out;               // [encoded 2048x2048 | decoded 2048x1024]

    float *Mm, *Xa, *Xb, *T, *Atb, *z0, *u0, *z1, *u1;
    cudaGetSymbolAddress((void**)&Mm,  g_M);
    cudaGetSymbolAddress((void**)&Xa,  g_Xa);
    cudaGetSymbolAddress((void**)&Xb,  g_Xb);
    cudaGetSymbolAddress((void**)&T,   g_T);
    cudaGetSymbolAddress((void**)&Atb, g_Atb);
    cudaGetSymbolAddress((void**)&z0,  g_z0);
    cudaGetSymbolAddress((void**)&u0,  g_u0);
    cudaGetSymbolAddress((void**)&z1,  g_z1);
    cudaGetSymbolAddress((void**)&u1,  g_u1);

    dim3 blk(256);
    dim3 grid_oo(OUTF / 128, OUTF / 128);   // 2048x2048 output
    dim3 grid_bo(OUTF / 128, BATCH / 128);  // batch x out
    dim3 grid_bi(INF / 128, BATCH / 128);   // batch x in

    // 1) M = W @ W^T + I     (NT, K = INF)
    reset_scalar_kernel<<<1, 1>>>();
    sgemm_kernel<true, 0, 0><<<grid_oo, blk>>>(
        W, nullptr, nullptr, W, nullptr, nullptr, Mm, nullptr,
        OUTF, OUTF, INF, 1.0f, 0.0f, 1.0f);

    // 2) s = ||M||_inf >= lambda_max;  X0 = (2/(s+1)) I
    row_abs_sum_max_kernel<<<OUTF, 256>>>(Mm, OUTF);
    init_X_kernel<<<(OUTF * OUTF) / 256, 256>>>(Xa, OUTF);

    // 3) Newton-Schulz: X <- 2X - X (M X)
    float* Xc = Xa;
    float* Xn = Xb;
    for (int it = 0; it < NEWTON_ITERS; it++) {
        sgemm_kernel<false, 0, 0><<<grid_oo, blk>>>(
            Mm, nullptr, nullptr, Xc, nullptr, nullptr, T, nullptr,
            OUTF, OUTF, OUTF, 1.0f, 0.0f, 0.0f);
        sgemm_kernel<false, 0, 0><<<grid_oo, blk>>>(
            Xc, nullptr, nullptr, T, Xc, nullptr, Xn, nullptr,
            OUTF, OUTF, OUTF, -1.0f, 2.0f, 0.0f);
        float* tmp = Xc; Xc = Xn; Xn = tmp;
    }
    // Xc now holds M^{-1}

    // 4) Atb = x @ W^T        (NT, K = INF)
    sgemm_kernel<true, 0, 0><<<grid_bo, blk>>>(
        x, nullptr, nullptr, W, nullptr, nullptr, Atb, nullptr,
        BATCH, OUTF, INF, 1.0f, 0.0f, 0.0f);

    // 5) z = u = 0
    zero2_kernel<<<(BATCH * OUTF) / (256 * 4), 256>>>(z0, u0);

    // 6) 100 fully-fused ADMM iterations:
    //    one GEMM: prologue r = Atb + z - u, body r @ M^{-1}, epilogue soft-threshold + dual
    float *zi = z0, *ui = u0, *zo = z1, *uo = u1;
    for (int it = 0; it < ADMM_ITERS; it++) {
        sgemm_kernel<false, 1, 1><<<grid_bo, blk>>>(
            Atb, zi, ui, Xc, nullptr, ui, zo, uo,
            BATCH, OUTF, OUTF, 1.0f, 0.0f, 0.0f);
        float* t;
        t = zi; zi = zo; zo = t;
        t = ui; ui = uo; uo = t;
    }
    // final z is in zi

    // 7) outputs: encoded = z ; decoded = z @ W (NN, K = OUTF, N = INF)
    cudaMemcpyAsync(out, zi, (size_t)BATCH * OUTF * sizeof(float),
                    cudaMemcpyDeviceToDevice, 0);
    sgemm_kernel<false, 0, 0><<<grid_bi, blk>>>(
        zi, nullptr, nullptr, W, nullptr, nullptr, out + (size_t)BATCH * OUTF, nullptr,
        BATCH, INF, OUTF, 1.0f, 0.0f, 0.0f);
}